// round 6
// baseline (speedup 1.0000x reference)
#include <cuda_runtime.h>
#include <math.h>

// Problem constants
#define BATCH 16
#define DEC   256
#define ENC   2048
#define DM    512
#define C2    1024   // 2*DM, encoder feature dim
#define C4    (C2/4) // 256 float4 per row

#define ECH   128           // E chunks
#define EPER  (ENC/ECH)     // 16 rows per chunk

#define CTX4  (BATCH * DEC * C2 / 4)   // 1048576 float4
#define ATT4  (BATCH * DEC * ENC / 4)  // 2097152 float4

// Scratch (allocation-free rule: __device__ globals)
__device__ float  g_venc[C2];
__device__ float  g_score[BATCH * ENC];
__device__ float  g_prob[BATCH * ENC];
__device__ float  g_m[ECH][BATCH];
__device__ float  g_z[ECH][BATCH];
__device__ float4 g_ctx_part[ECH][BATCH][C4];  // 8 MB
__device__ float4 g_ctx[BATCH][C4];            // 64 KB

// ---------------------------------------------------------------------------
// Kernel 1: v_enc[c] = sum_m W_enc[c,m] * w_out[m]
// ---------------------------------------------------------------------------
__global__ void venc_kernel(const float* __restrict__ W_enc,
                            const float* __restrict__ w_out) {
    int c = blockIdx.x * blockDim.x + threadIdx.x;
    if (c >= C2) return;
    const float4* row = (const float4*)(W_enc + (size_t)c * DM);
    const float4* w4  = (const float4*)w_out;
    float acc = 0.f;
#pragma unroll 8
    for (int i = 0; i < DM / 4; i++) {
        float4 a = row[i];
        float4 b = w4[i];
        acc += a.x * b.x + a.y * b.y + a.z * b.z + a.w * b.w;
    }
    g_venc[c] = acc;
}

// ---------------------------------------------------------------------------
// Kernel 2 (FUSED, L2-reuse): block = (chunk ch, batch b), 256 threads.
// Pass 1: warp-per-row scores (DRAM read). venc in regs (L1-hot).
// Softmax: every warp redundantly reduces the 16 chunk scores (no idle phase).
// Pass 2: ctx partial, re-reading the chunk (L2 hit; proven R2 access pattern).
// All warp collectives run with the entire warp active.
// ---------------------------------------------------------------------------
__global__ void __launch_bounds__(256)
fused_kernel(const float4* __restrict__ enc4,
             const float* __restrict__ emask) {
    int ch = blockIdx.x;   // 0..127
    int b  = blockIdx.y;   // 0..15
    int t  = threadIdx.x;  // 0..255
    int lane = t & 31, wid = t >> 5;

    __shared__ float ss[EPER];   // masked scores
    __shared__ float sw[EPER];   // softmax weights exp(s - m_loc)

    const int rowbase = b * ENC + ch * EPER;     // first global row of chunk

    // venc slice for this lane (same for both rows it reduces); L1-hot
    float4 vv[8];
#pragma unroll
    for (int i = 0; i < 8; i++)
        vv[i] = __ldg(((const float4*)g_venc) + lane + 32 * i);

    // ---- Pass 1: scores. warp wid handles rows 2*wid and 2*wid+1 ----
#pragma unroll
    for (int k = 0; k < 2; k++) {
        int r  = wid * 2 + k;
        int eg = rowbase + r;
        const float4* row = enc4 + (size_t)eg * C4;
        float s = 0.f;
#pragma unroll
        for (int i = 0; i < 8; i++) {
            float4 a = __ldg(row + lane + 32 * i);
            s += a.x * vv[i].x + a.y * vv[i].y + a.z * vv[i].z + a.w * vv[i].w;
        }
#pragma unroll
        for (int o = 16; o > 0; o >>= 1)
            s += __shfl_xor_sync(0xffffffffu, s, o);
        if (lane == 0) {
            s += logf(emask[eg]);
            g_score[eg] = s;
            ss[r] = s;
        }
    }
    __syncthreads();

    // ---- Local softmax over 16 scores, redundantly in every warp ----
    {
        float s = (lane < EPER) ? ss[lane] : -1e30f;
        float m = s;
#pragma unroll
        for (int o = 16; o > 0; o >>= 1)
            m = fmaxf(m, __shfl_xor_sync(0xffffffffu, m, o));
        float w = (lane < EPER) ? expf(s - m) : 0.f;
        float z = w;
#pragma unroll
        for (int o = 16; o > 0; o >>= 1)
            z += __shfl_xor_sync(0xffffffffu, z, o);
        if (wid == 0) {
            if (lane < EPER) sw[lane] = w;
            if (lane == 0) { g_m[ch][b] = m; g_z[ch][b] = z; }
        }
    }
    __syncthreads();

    // ---- Pass 2: ctx partial; chunk is L2-resident (just read above) ----
    const float4* base = enc4 + (size_t)rowbase * C4 + t;
    float4 acc = make_float4(0.f, 0.f, 0.f, 0.f);
#pragma unroll
    for (int e = 0; e < EPER; e++) {
        float4 v = __ldg(base + (size_t)e * C4);
        float w = sw[e];
        acc.x += w * v.x;
        acc.y += w * v.y;
        acc.z += w * v.z;
        acc.w += w * v.w;
    }
    g_ctx_part[ch][b][t] = acc;
}

// ---------------------------------------------------------------------------
// Kernel 3 (COMBINE): per batch b:
//   M = max_ch m_ch;  Z = sum_ch z_ch * exp(m_ch - M)
//   ctx[b][c] = (sum_ch part_ch[c] * exp(m_ch - M)) / Z
//   prob[b][e] = exp(score[b][e] - M) / Z
// All shuffles full-warp.
// ---------------------------------------------------------------------------
__global__ void combine_kernel() {
    int b = blockIdx.x;
    int t = threadIdx.x;   // 0..255
    int lane = t & 31, wid = t >> 5;

    __shared__ float sc[ECH];    // per-chunk scale exp(m_ch - M) / Z
    __shared__ float redm[8];
    __shared__ float redz[8];
    __shared__ float sMZ[2];

    float m_t = (t < ECH) ? g_m[t][b] : -1e30f;
    float z_t = (t < ECH) ? g_z[t][b] : 0.f;

    float m = m_t;
#pragma unroll
    for (int o = 16; o > 0; o >>= 1)
        m = fmaxf(m, __shfl_xor_sync(0xffffffffu, m, o));
    if (lane == 0) redm[wid] = m;
    __syncthreads();

    if (wid == 0) {
        float v = (lane < 8) ? redm[lane] : -1e30f;
#pragma unroll
        for (int o = 16; o > 0; o >>= 1)
            v = fmaxf(v, __shfl_xor_sync(0xffffffffu, v, o));
        if (lane == 0) sMZ[0] = v;
    }
    __syncthreads();
    float M = sMZ[0];

    float zs = z_t * expf(m_t - M);
#pragma unroll
    for (int o = 16; o > 0; o >>= 1)
        zs += __shfl_xor_sync(0xffffffffu, zs, o);
    if (lane == 0) redz[wid] = zs;
    __syncthreads();

    if (wid == 0) {
        float v = (lane < 8) ? redz[lane] : 0.f;
#pragma unroll
        for (int o = 16; o > 0; o >>= 1)
            v += __shfl_xor_sync(0xffffffffu, v, o);
        if (lane == 0) sMZ[1] = v;
    }
    __syncthreads();
    float invZ = 1.f / sMZ[1];

    if (t < ECH) sc[t] = expf(m_t - M) * invZ;
    __syncthreads();

    float4 acc = make_float4(0.f, 0.f, 0.f, 0.f);
#pragma unroll 8
    for (int ch = 0; ch < ECH; ch++) {
        float4 v = g_ctx_part[ch][b][t];
        float s = sc[ch];
        acc.x += s * v.x;
        acc.y += s * v.y;
        acc.z += s * v.z;
        acc.w += s * v.w;
    }
    g_ctx[b][t] = acc;

#pragma unroll
    for (int i = 0; i < 8; i++) {
        int e = t + 256 * i;
        g_prob[b * ENC + e] = expf(g_score[b * ENC + e] - M) * invZ;
    }
}

// ---------------------------------------------------------------------------
// Kernel 4 (WRITER): both broadcast outputs in one grid.
//   out_ctx[b,d,c]  = g_ctx[b][c]    (16.8 MB)
//   out_attn[b,d,e] = g_prob[b][e]   (33.5 MB)
// ---------------------------------------------------------------------------
__global__ void writer_kernel(float4* __restrict__ out_ctx,
                              float4* __restrict__ out_attn) {
    int i4 = blockIdx.x * blockDim.x + threadIdx.x;
    if (i4 < CTX4) {
        int row = i4 >> 8;         // 256 float4 per row
        int c4  = i4 & 255;
        int b   = row >> 8;        // / DEC
        out_ctx[i4] = g_ctx[b][c4];
    } else {
        int j4 = i4 - CTX4;
        if (j4 >= ATT4) return;
        int row = j4 >> 9;         // 512 float4 per row
        int e4  = j4 & 511;
        int b   = row >> 8;        // / DEC
        out_attn[j4] = ((const float4*)g_prob)[b * 512 + e4];
    }
}

// ---------------------------------------------------------------------------
// Launch. Inputs: decoder_states, decoder_mask, encoder_states, encoder_mask,
//   W_enc, W_dec, w_out, b_out
// Output: [context (B*DEC*C2) | attn_dist (B*DEC*ENC)] floats
// ---------------------------------------------------------------------------
extern "C" void kernel_launch(void* const* d_in, const int* in_sizes, int n_in,
                              void* d_out, int out_size) {
    const float* enc   = (const float*)d_in[2];
    const float* emask = (const float*)d_in[3];
    const float* W_enc = (const float*)d_in[4];
    const float* w_out = (const float*)d_in[6];

    float* out_ctx  = (float*)d_out;
    float* out_attn = (float*)d_out + (size_t)BATCH * DEC * C2;

    venc_kernel<<<C2 / 128, 128>>>(W_enc, w_out);

    dim3 gf(ECH, BATCH);
    fused_kernel<<<gf, 256>>>((const float4*)enc, emask);

    combine_kernel<<<BATCH, 256>>>();

    writer_kernel<<<(CTX4 + ATT4 + 255) / 256, 256>>>((float4*)out_ctx,
                                                      (float4*)out_attn);
}

// round 9
// speedup vs baseline: 1.0407x; 1.0407x over previous
#include <cuda_runtime.h>
#include <math.h>

// Problem constants
#define BATCH 16
#define DEC   256
#define ENC   2048
#define DM    512
#define C2    1024   // 2*DM, encoder feature dim
#define C4    (C2/4) // 256 float4 per row

#define ECH   32            // E chunks (proven ctx_partial geometry)
#define EPER  (ENC/ECH)     // 64 rows per chunk

#define CTX4  (BATCH * DEC * C2 / 4)   // 1048576 float4
#define ATT4  (BATCH * DEC * ENC / 4)  // 2097152 float4

// Scratch (allocation-free rule: __device__ globals)
__device__ float  g_venc[C2];
__device__ float  g_score[BATCH * ENC];
__device__ float  g_prob[BATCH * ENC];
__device__ float4 g_ctx_part[ECH][BATCH][C4];  // 2 MB
__device__ float4 g_ctx[BATCH][C4];            // 64 KB

// ---------------------------------------------------------------------------
// Kernel 1: v_enc[c] = sum_m W_enc[c,m] * w_out[m]
// ---------------------------------------------------------------------------
__global__ void venc_kernel(const float* __restrict__ W_enc,
                            const float* __restrict__ w_out) {
    int c = blockIdx.x * blockDim.x + threadIdx.x;
    if (c >= C2) return;
    const float4* row = (const float4*)(W_enc + (size_t)c * DM);
    const float4* w4  = (const float4*)w_out;
    float acc = 0.f;
#pragma unroll 8
    for (int i = 0; i < DM / 4; i++) {
        float4 a = row[i];
        float4 b = w4[i];
        acc += a.x * b.x + a.y * b.y + a.z * b.z + a.w * b.w;
    }
    g_venc[c] = acc;
}

// ---------------------------------------------------------------------------
// Kernel 2: SCORES, thread-per-column streaming (ctx_partial load geometry).
// Block = (chunk of 64 rows, batch), 256 threads. Thread t owns float4 col t,
// streams 64 rows in 4 bursts of 16; per burst: 16 independent float4 loads
// + 16 reg partial dots, then 16 full-warp shuffle reduces into smem.
// venc slice = ONE register float4 per thread (loaded once).
// ---------------------------------------------------------------------------
__global__ void __launch_bounds__(256)
scores_kernel(const float4* __restrict__ enc4,
              const float* __restrict__ emask) {
    int ch = blockIdx.x;   // 0..31
    int b  = blockIdx.y;   // 0..15
    int t  = threadIdx.x;  // 0..255
    int lane = t & 31, wid = t >> 5;

    __shared__ float wsum[EPER][8];   // per-row per-warp partials (2 KB)

    const int rowbase = b * ENC + ch * EPER;
    float4 v4 = __ldg(((const float4*)g_venc) + t);
    const float4* base = enc4 + (size_t)rowbase * C4 + t;

#pragma unroll
    for (int g = 0; g < 4; g++) {
        float p[16];
#pragma unroll
        for (int e = 0; e < 16; e++) {
            float4 r = __ldg(base + (size_t)(g * 16 + e) * C4);
            p[e] = r.x * v4.x + r.y * v4.y + r.z * v4.z + r.w * v4.w;
        }
#pragma unroll
        for (int e = 0; e < 16; e++) {
            float s = p[e];
#pragma unroll
            for (int o = 16; o > 0; o >>= 1)
                s += __shfl_xor_sync(0xffffffffu, s, o);
            if (lane == 0) wsum[g * 16 + e][wid] = s;
        }
    }
    __syncthreads();

    if (t < EPER) {
        float s = 0.f;
#pragma unroll
        for (int w = 0; w < 8; w++) s += wsum[t][w];
        int eg = rowbase + t;
        g_score[eg] = s + logf(emask[eg]);
    }
}

// ---------------------------------------------------------------------------
// Kernel 3: softmax over E per batch (R2-proven). 16 blocks x 1024 threads.
// ---------------------------------------------------------------------------
__global__ void softmax_kernel() {
    int b = blockIdx.x;
    int t = threadIdx.x;            // 0..1023
    __shared__ float red[32];

    float s0 = g_score[b * ENC + t];
    float s1 = g_score[b * ENC + 1024 + t];

    float m = fmaxf(s0, s1);
#pragma unroll
    for (int o = 16; o > 0; o >>= 1)
        m = fmaxf(m, __shfl_xor_sync(0xffffffffu, m, o));
    if ((t & 31) == 0) red[t >> 5] = m;
    __syncthreads();
    if (t < 32) {
        float v = red[t];
#pragma unroll
        for (int o = 16; o > 0; o >>= 1)
            v = fmaxf(v, __shfl_xor_sync(0xffffffffu, v, o));
        red[t] = v;
    }
    __syncthreads();
    m = red[0];

    float e0 = expf(s0 - m);
    float e1 = expf(s1 - m);

    float s = e0 + e1;
    __syncthreads();
#pragma unroll
    for (int o = 16; o > 0; o >>= 1)
        s += __shfl_xor_sync(0xffffffffu, s, o);
    if ((t & 31) == 0) red[t >> 5] = s;
    __syncthreads();
    if (t < 32) {
        float v = red[t];
#pragma unroll
        for (int o = 16; o > 0; o >>= 1)
            v += __shfl_xor_sync(0xffffffffu, v, o);
        red[t] = v;
    }
    __syncthreads();
    float inv = 1.f / red[0];

    g_prob[b * ENC + t]        = e0 * inv;
    g_prob[b * ENC + 1024 + t] = e1 * inv;
}

// ---------------------------------------------------------------------------
// Kernel 4: ctx partial (R2-proven, 25.3us @67% DRAM).
// grid (ECH=32, BATCH=16), 256 threads; thread t owns float4 col t, 64 rows.
// ---------------------------------------------------------------------------
__global__ void ctx_partial_kernel(const float4* __restrict__ enc4) {
    int ch = blockIdx.x;   // 0..31
    int b  = blockIdx.y;   // 0..15
    int t  = threadIdx.x;  // 0..255

    __shared__ float sp[EPER];
    if (t < EPER) sp[t] = g_prob[b * ENC + ch * EPER + t];
    __syncthreads();

    const float4* base = enc4 + ((size_t)(b * ENC + ch * EPER)) * C4 + t;
    float4 acc = make_float4(0.f, 0.f, 0.f, 0.f);
#pragma unroll 8
    for (int e = 0; e < EPER; e++) {
        float4 v = __ldg(base + (size_t)e * C4);
        float p = sp[e];
        acc.x += p * v.x;
        acc.y += p * v.y;
        acc.z += p * v.z;
        acc.w += p * v.w;
    }
    g_ctx_part[ch][b][t] = acc;
}

// ---------------------------------------------------------------------------
// Kernel 4b: reduce 32 partials -> g_ctx[b][c4]. grid 16, block 256. 2MB L2.
// ---------------------------------------------------------------------------
__global__ void ctx_reduce_kernel() {
    int b = blockIdx.x;
    int t = threadIdx.x;
    float4 acc = make_float4(0.f, 0.f, 0.f, 0.f);
#pragma unroll
    for (int ch = 0; ch < ECH; ch++) {
        float4 v = g_ctx_part[ch][b][t];
        acc.x += v.x; acc.y += v.y; acc.z += v.z; acc.w += v.w;
    }
    g_ctx[b][t] = acc;
}

// ---------------------------------------------------------------------------
// Kernel 5: WRITER, grid-stride x4 (both broadcast outputs in one grid).
//   out_ctx[b,d,c]  = g_ctx[b][c]    (16.8 MB)
//   out_attn[b,d,e] = g_prob[b][e]   (33.5 MB)
// ---------------------------------------------------------------------------
__global__ void writer_kernel(float4* __restrict__ out_ctx,
                              float4* __restrict__ out_attn) {
    const int total  = CTX4 + ATT4;
    const int stride = gridDim.x * blockDim.x;
    for (int i4 = blockIdx.x * blockDim.x + threadIdx.x; i4 < total; i4 += stride) {
        if (i4 < CTX4) {
            int row = i4 >> 8;         // 256 float4 per row
            int c4  = i4 & 255;
            int b   = row >> 8;        // / DEC
            out_ctx[i4] = g_ctx[b][c4];
        } else {
            int j4 = i4 - CTX4;
            int row = j4 >> 9;         // 512 float4 per row
            int e4  = j4 & 511;
            int b   = row >> 8;        // / DEC
            out_attn[j4] = ((const float4*)g_prob)[b * 512 + e4];
        }
    }
}

// ---------------------------------------------------------------------------
// Launch. Inputs: decoder_states, decoder_mask, encoder_states, encoder_mask,
//   W_enc, W_dec, w_out, b_out
// Output: [context (B*DEC*C2) | attn_dist (B*DEC*ENC)] floats
// ---------------------------------------------------------------------------
extern "C" void kernel_launch(void* const* d_in, const int* in_sizes, int n_in,
                              void* d_out, int out_size) {
    const float* enc   = (const float*)d_in[2];
    const float* emask = (const float*)d_in[3];
    const float* W_enc = (const float*)d_in[4];
    const float* w_out = (const float*)d_in[6];

    float* out_ctx  = (float*)d_out;
    float* out_attn = (float*)d_out + (size_t)BATCH * DEC * C2;

    venc_kernel<<<C2 / 128, 128>>>(W_enc, w_out);

    dim3 gs(ECH, BATCH);
    scores_kernel<<<gs, 256>>>((const float4*)enc, emask);

    softmax_kernel<<<BATCH, 1024>>>();

    ctx_partial_kernel<<<gs, 256>>>((const float4*)enc);
    ctx_reduce_kernel<<<BATCH, 256>>>();

    // grid-stride writer: 4 float4 per thread
    writer_kernel<<<(CTX4 + ATT4) / (4 * 256), 256>>>((float4*)out_ctx,
                                                      (float4*)out_attn);
}